// round 6
// baseline (speedup 1.0000x reference)
#include <cuda_runtime.h>
#include <cuda_fp16.h>
#include <cstdint>

// Problem constants
#define BB 128
#define TT 256
#define DD 768
#define SS 128
#define NROWS (BB*TT)   // 32768

// Scratch (allocation-free rule: __device__ globals)
__device__ float  g_Bx[NROWS * SS];        // f32: feeds scan
__device__ __half g_states_h[NROWS * SS];
__device__ __half g_xh[NROWS * DD];
__device__ __half g_Bw_h[SS * DD];
__device__ __half g_Cw_h[DD * SS];
__device__ __half g_Dw_h[DD * DD];

// ---------------------------------------------------------------------------
// helpers
// ---------------------------------------------------------------------------
__device__ __forceinline__ uint32_t packh2(float lo, float hi) {
    __half2 h = __floats2half2_rn(lo, hi);
    return *(uint32_t*)&h;
}
__device__ __forceinline__ void mma16(float* c, const uint32_t* a, const uint32_t* b) {
    asm volatile(
        "mma.sync.aligned.m16n8k16.row.col.f32.f16.f16.f32 "
        "{%0,%1,%2,%3}, {%4,%5,%6,%7}, {%8,%9}, {%0,%1,%2,%3};"
        : "+f"(c[0]), "+f"(c[1]), "+f"(c[2]), "+f"(c[3])
        : "r"(a[0]), "r"(a[1]), "r"(a[2]), "r"(a[3]),
          "r"(b[0]), "r"(b[1]));
}

// Swizzled smem layout for a [rows x 32] fp16 tile:
//   logical (r, k) -> phys row p = r>>1 (128B), chunk q = ((r&1)*4 + k/8) ^ (p&7)
__device__ __forceinline__ uint32_t sw_off(int r, int k) {
    int p = r >> 1;
    int q = (((r & 1) << 2) | (k >> 3)) ^ (p & 7);
    return (uint32_t)((p << 7) + (q << 4) + ((k & 7) << 1));
}

// ---------------------------------------------------------------------------
// fp16 GEMM, two K segments, cp.async 3-stage pipeline + ldmatrix fragments.
//   C[M, 128-col-tile] = A0[M,K0] @ W0[.,K0]^T + A1[M,K1] @ W1[.,K1]^T  (f32 out)
// ---------------------------------------------------------------------------
template<int BM>
__global__ void __launch_bounds__(BM * 2, 256 / BM)
gemm_ca(const __half* __restrict__ A0, const __half* __restrict__ W0, int K0,
        const __half* __restrict__ A1, const __half* __restrict__ W1, int K1,
        float* __restrict__ Cp, int ldc)
{
    constexpr int THREADS = BM * 2;
    constexpr int ABYTES  = BM * 64;      // BM rows x 32 fp16
    constexpr int BBYTES  = 128 * 64;
    constexpr int STAGE   = ABYTES + BBYTES;
    __shared__ __align__(1024) char smem[3 * STAGE];

    const int tid  = threadIdx.x;
    const int lane = tid & 31;
    const int wid  = tid >> 5;
    const int wm   = wid >> 1;
    const int wn   = wid & 1;
    const int rowBlock = blockIdx.y * BM;
    const int colBlock = blockIdx.x * 128;

    const int NC0 = K0 >> 5;
    const int NT  = NC0 + (K1 >> 5);

    const uint32_t sbase = (uint32_t)__cvta_generic_to_shared(smem);

    float acc[2][8][4];
#pragma unroll
    for (int mi = 0; mi < 2; ++mi)
#pragma unroll
        for (int ni = 0; ni < 8; ++ni)
#pragma unroll
            for (int j = 0; j < 4; ++j) acc[mi][ni][j] = 0.f;

    auto issue_loads = [&](int t) {
        const __half *Ap, *Wp; int K, kb;
        if (t < NC0) { Ap = A0; Wp = W0; K = K0; kb = t << 5; }
        else         { Ap = A1; Wp = W1; K = K1; kb = (t - NC0) << 5; }
        const uint32_t st = sbase + (t % 3) * STAGE;
#pragma unroll
        for (int ch = tid; ch < BM * 4; ch += THREADS) {
            const int r = ch >> 2, c = ch & 3;
            const __half* src = Ap + (size_t)(rowBlock + r) * K + kb + c * 8;
            const uint32_t dst = st + sw_off(r, c * 8);
            asm volatile("cp.async.cg.shared.global [%0], [%1], 16;"
                         :: "r"(dst), "l"(src));
        }
#pragma unroll
        for (int ch = tid; ch < 512; ch += THREADS) {
            const int r = ch >> 2, c = ch & 3;
            const __half* src = Wp + (size_t)(colBlock + r) * K + kb + c * 8;
            const uint32_t dst = st + ABYTES + sw_off(r, c * 8);
            asm volatile("cp.async.cg.shared.global [%0], [%1], 16;"
                         :: "r"(dst), "l"(src));
        }
        asm volatile("cp.async.commit_group;" ::: "memory");
    };

    issue_loads(0);
    issue_loads(1);

    for (int t = 0; t < NT; ++t) {
        asm volatile("cp.async.wait_group 1;" ::: "memory");
        __syncthreads();
        const uint32_t Abase = sbase + (t % 3) * STAGE;
        const uint32_t Bbase = Abase + ABYTES;

#pragma unroll
        for (int kf = 0; kf < 2; ++kf) {
            uint32_t af[2][4];
#pragma unroll
            for (int mi = 0; mi < 2; ++mi) {
                const int row = wm * 32 + mi * 16 + (lane & 7) + ((lane >> 3) & 1) * 8;
                const int kb  = kf * 16 + ((lane >> 4) & 1) * 8;
                const uint32_t addr = Abase + sw_off(row, kb);
                asm volatile("ldmatrix.sync.aligned.m8n8.x4.shared.b16 {%0,%1,%2,%3}, [%4];"
                             : "=r"(af[mi][0]), "=r"(af[mi][1]),
                               "=r"(af[mi][2]), "=r"(af[mi][3]) : "r"(addr));
            }
            uint32_t bf[8][2];
#pragma unroll
            for (int nj = 0; nj < 4; ++nj) {
                const int n  = wn * 64 + nj * 16 + (lane & 7) + ((lane >> 4) & 1) * 8;
                const int kb = kf * 16 + ((lane >> 3) & 1) * 8;
                const uint32_t addr = Bbase + sw_off(n, kb);
                uint32_t q0, q1, q2, q3;
                asm volatile("ldmatrix.sync.aligned.m8n8.x4.shared.b16 {%0,%1,%2,%3}, [%4];"
                             : "=r"(q0), "=r"(q1), "=r"(q2), "=r"(q3) : "r"(addr));
                bf[nj * 2][0] = q0;     bf[nj * 2][1] = q1;
                bf[nj * 2 + 1][0] = q2; bf[nj * 2 + 1][1] = q3;
            }
            if (kf == 0 && t + 2 < NT) issue_loads(t + 2);
#pragma unroll
            for (int mi = 0; mi < 2; ++mi)
#pragma unroll
                for (int ni = 0; ni < 8; ++ni)
                    mma16(acc[mi][ni], af[mi], bf[ni]);
        }
        __syncthreads();
    }

    const int g  = lane & 3;
    const int qr = lane >> 2;
#pragma unroll
    for (int mi = 0; mi < 2; ++mi)
#pragma unroll
        for (int ni = 0; ni < 8; ++ni) {
            const int r = rowBlock + wm * 32 + mi * 16 + qr;
            const int c = colBlock + wn * 64 + ni * 8 + 2 * g;
            *(float2*)&Cp[(size_t)r * ldc + c]       = make_float2(acc[mi][ni][0], acc[mi][ni][1]);
            *(float2*)&Cp[(size_t)(r + 8) * ldc + c] = make_float2(acc[mi][ni][2], acc[mi][ni][3]);
        }
}

// ---------------------------------------------------------------------------
// Conversions f32 -> fp16
// ---------------------------------------------------------------------------
__global__ void __launch_bounds__(256)
convert_x_kernel(const float* __restrict__ x)
{
    const size_t i = ((size_t)blockIdx.x * 256 + threadIdx.x) * 8;
    float4 f0 = *(const float4*)(x + i);
    float4 f1 = *(const float4*)(x + i + 4);
    uint4 o;
    o.x = packh2(f0.x, f0.y); o.y = packh2(f0.z, f0.w);
    o.z = packh2(f1.x, f1.y); o.w = packh2(f1.z, f1.w);
    *(uint4*)(g_xh + i) = o;
}

__global__ void __launch_bounds__(256)
convert_w_kernel(const float* __restrict__ Bw,
                 const float* __restrict__ Cw,
                 const float* __restrict__ Dw)
{
    const int i = blockIdx.x * blockDim.x + threadIdx.x;
    if (i < SS * DD) g_Bw_h[i] = __float2half(Bw[i]);
    if (i < DD * SS) g_Cw_h[i] = __float2half(Cw[i]);
    if (i < DD * DD) g_Dw_h[i] = __float2half(Dw[i]);
}

// ---------------------------------------------------------------------------
// Sequential scan, latency-optimized:
//   one CTA per batch, 128 threads, thread s owns state element s.
//   A row s in registers as 64 packed f32x2 operands; full 128-MAC dot per
//   thread via fma.rn.f32x2 (dual-fp32, sm_100+ base ISA). st reads are
//   all-lane broadcasts (conflict-free); double-buffered st => ONE barrier
//   per timestep; bx prefetched 2 steps ahead (Bx is L2-resident).
// ---------------------------------------------------------------------------
__global__ void __launch_bounds__(128)
scan_kernel(const float* __restrict__ A)
{
    __shared__ __align__(16) float st[2][SS];

    const int s = threadIdx.x;
    const int b = blockIdx.x;

    // A row s -> 64 packed f32x2 regs ({A[s][2j], A[s][2j+1]})
    unsigned long long a[64];
    const ulonglong2* ar = (const ulonglong2*)(A + (size_t)s * SS);
#pragma unroll
    for (int j = 0; j < 32; ++j) {
        ulonglong2 v = ar[j];
        a[2 * j]     = v.x;
        a[2 * j + 1] = v.y;
    }

    st[0][s] = 0.f;

    const float* bx = g_Bx + (size_t)b * TT * SS + s;
    __half* so = g_states_h + (size_t)b * TT * SS + s;

    float bx0 = bx[0];
    float bx1 = bx[SS];
    __syncthreads();

#pragma unroll 1
    for (int t = 0; t < TT; ++t) {
        const int p = t & 1;
        const unsigned long long* stv = (const unsigned long long*)st[p];

        unsigned long long acc0 = 0ull, acc1 = 0ull, acc2 = 0ull, acc3 = 0ull;
#pragma unroll
        for (int j = 0; j < 16; ++j) {
            asm("fma.rn.f32x2 %0, %1, %2, %0;" : "+l"(acc0) : "l"(a[4*j]),     "l"(stv[4*j]));
            asm("fma.rn.f32x2 %0, %1, %2, %0;" : "+l"(acc1) : "l"(a[4*j + 1]), "l"(stv[4*j + 1]));
            asm("fma.rn.f32x2 %0, %1, %2, %0;" : "+l"(acc2) : "l"(a[4*j + 2]), "l"(stv[4*j + 2]));
            asm("fma.rn.f32x2 %0, %1, %2, %0;" : "+l"(acc3) : "l"(a[4*j + 3]), "l"(stv[4*j + 3]));
        }
        unsigned long long s01, s23, sall;
        asm("add.rn.f32x2 %0, %1, %2;" : "=l"(s01)  : "l"(acc0), "l"(acc1));
        asm("add.rn.f32x2 %0, %1, %2;" : "=l"(s23)  : "l"(acc2), "l"(acc3));
        asm("add.rn.f32x2 %0, %1, %2;" : "=l"(sall) : "l"(s01),  "l"(s23));
        const float lo = __uint_as_float((uint32_t)sall);
        const float hi = __uint_as_float((uint32_t)(sall >> 32));

        float v = lo + hi + bx0;
        v = fminf(fmaxf(v, -10.f), 10.f);

        st[p ^ 1][s] = v;
        so[(size_t)t * SS] = __float2half(v);

        bx0 = bx1;
        if (t + 2 < TT) bx1 = bx[(size_t)(t + 2) * SS];

        __syncthreads();
    }
}

// ---------------------------------------------------------------------------
// Fused gate + residual mix + LayerNorm. One block (128 threads) per row.
// ---------------------------------------------------------------------------
__global__ void __launch_bounds__(128)
mix_ln_kernel(const float* __restrict__ x,
              const float* __restrict__ gate_w,
              const float* __restrict__ gate_b,
              const float* __restrict__ gamma,
              const float* __restrict__ beta,
              float* __restrict__ io)
{
    __shared__ float red[4][2];

    const int row = blockIdx.x;
    const int tid = threadIdx.x;
    const int lane = tid & 31, w = tid >> 5;
    const float* xr = x + (size_t)row * DD;
    float* tr = io + (size_t)row * DD;

    float xs[6], ts[6];
    float l0 = 0.f, l1 = 0.f;
#pragma unroll
    for (int k = 0; k < 6; ++k) {
        const int i = tid + k * 128;
        xs[k] = xr[i];
        ts[k] = tr[i];
        l0 = fmaf(xs[k], gate_w[i], l0);
        l1 = fmaf(xs[k], gate_w[DD + i], l1);
    }
#pragma unroll
    for (int o = 16; o; o >>= 1) {
        l0 += __shfl_xor_sync(0xffffffffu, l0, o);
        l1 += __shfl_xor_sync(0xffffffffu, l1, o);
    }
    if (lane == 0) { red[w][0] = l0; red[w][1] = l1; }
    __syncthreads();
    l0 = red[0][0] + red[1][0] + red[2][0] + red[3][0] + gate_b[0];
    l1 = red[0][1] + red[1][1] + red[2][1] + red[3][1] + gate_b[1];

    const float mx = fmaxf(l0, l1);
    const float e0 = expf(l0 - mx), e1 = expf(l1 - mx);
    const float inv = 1.f / (e0 + e1);
    const float g0 = e0 * inv, g1 = e1 * inv;

    float mix[6];
    float s = 0.f, s2 = 0.f;
#pragma unroll
    for (int k = 0; k < 6; ++k) {
        mix[k] = g0 * ts[k] + g1 * xs[k];
        s += mix[k];
        s2 = fmaf(mix[k], mix[k], s2);
    }
    __syncthreads();
#pragma unroll
    for (int o = 16; o; o >>= 1) {
        s  += __shfl_xor_sync(0xffffffffu, s, o);
        s2 += __shfl_xor_sync(0xffffffffu, s2, o);
    }
    if (lane == 0) { red[w][0] = s; red[w][1] = s2; }
    __syncthreads();
    s  = red[0][0] + red[1][0] + red[2][0] + red[3][0];
    s2 = red[0][1] + red[1][1] + red[2][1] + red[3][1];

    const float mu = s * (1.f / DD);
    float var = s2 * (1.f / DD) - mu * mu;
    var = fmaxf(var, 0.f);
    const float rstd = rsqrtf(var + 1e-5f);

#pragma unroll
    for (int k = 0; k < 6; ++k) {
        const int i = tid + k * 128;
        tr[i] = (mix[k] - mu) * rstd * gamma[i] + beta[i];
    }
}

// ---------------------------------------------------------------------------
// Launch
// ---------------------------------------------------------------------------
extern "C" void kernel_launch(void* const* d_in, const int* in_sizes, int n_in,
                              void* d_out, int out_size)
{
    const float* x      = (const float*)d_in[0];
    const float* A      = (const float*)d_in[1];
    const float* B_w    = (const float*)d_in[2];
    const float* C_w    = (const float*)d_in[3];
    const float* D_w    = (const float*)d_in[4];
    const float* gate_w = (const float*)d_in[5];
    const float* gate_b = (const float*)d_in[6];
    const float* gamma  = (const float*)d_in[7];
    const float* beta   = (const float*)d_in[8];
    float* out = (float*)d_out;

    float  *Bx = nullptr;
    __half *Sh = nullptr, *Xh = nullptr, *BwH = nullptr, *CwH = nullptr, *DwH = nullptr;
    cudaGetSymbolAddress((void**)&Bx,  g_Bx);
    cudaGetSymbolAddress((void**)&Sh,  g_states_h);
    cudaGetSymbolAddress((void**)&Xh,  g_xh);
    cudaGetSymbolAddress((void**)&BwH, g_Bw_h);
    cudaGetSymbolAddress((void**)&CwH, g_Cw_h);
    cudaGetSymbolAddress((void**)&DwH, g_Dw_h);

    // 0) conversions f32 -> fp16
    convert_x_kernel<<<(NROWS * DD) / (256 * 8), 256>>>(x);
    convert_w_kernel<<<(DD * DD + 255) / 256, 256>>>(B_w, C_w, D_w);

    // 1) Bx = x_h @ B_w^T   [32768 x 128], K=768; BM=64 tiles for wave balance
    gemm_ca<64><<<dim3(1, NROWS / 64), 128>>>(
        Xh, BwH, DD, Xh, BwH, 0, Bx, SS);

    // 2) sequential scan -> states (fp16)
    scan_kernel<<<BB, 128>>>(A);

    // 3) out = states_h @ C_w^T + x_h @ D_w^T   [32768 x 768], K = 128 + 768
    gemm_ca<128><<<dim3(DD / 128, NROWS / 128), 256>>>(
        Sh, CwH, SS, Xh, DwH, DD, out, DD);

    // 4) gate + residual mix + LayerNorm (in place on d_out)
    mix_ln_kernel<<<NROWS, 128>>>(x, gate_w, gate_b, gamma, beta, out);
}